// round 2
// baseline (speedup 1.0000x reference)
#include <cuda_runtime.h>
#include <cuda_bf16.h>

// Shapes
#define Bn 16
#define Tn 128
#define In 8
#define Dn 128
#define NT 2048           // Tn * Bn tokens, t = r*16 + b

// Output packing (fp32 concat of the reference tuple)
#define EMB_SZ   (NT*Dn)        // 262144
#define PAD_OFF  (EMB_SZ)       // padding_mask (B,T)
#define SEQ_OFF  (PAD_OFF+2048) // sequence_mask (T,B,1)
#define GLB_OFF  (SEQ_OFF+2048) // global_mask (T)
#define OUT_ALL  (GLB_OFF+128)  // 266368

// ---------------- scratch (device globals: allocation-free) ----------------
__device__ float g_M1[Dn*Dn];   // Wq @ Wk^T
__device__ float g_M2[Dn*Dn];   // Wv @ W_out
__device__ float g_Xd[NT*Dn];   // LN'd diagonal tokens
__device__ float g_Qp[NT*Dn];   // x_diag @ M1 / sqrt(D)
__device__ float g_Y [NT*Dn];   // softmax-weighted sum of x rows
__device__ float g_seq[NT];     // seq[r,b] as 0/1
__device__ int   g_mask_mode;   // 0=byte, 1=int32, 2=float32

// ---------------- helpers ----------------
__device__ __forceinline__ float gelu_f(float x) {
    // gelu(x) = x * sigmoid(2*0.79788456*(x + 0.044715 x^3)); 2 MUFU (EX2+RCP)
    float u2 = 1.5957691216057308f * fmaf(0.044715f * x, x * x, x);
    return __fdividef(x, 1.0f + __expf(-u2));
}

__device__ __forceinline__ float mask_at(const void* m, int idx, int mode) {
    if (mode == 0) return ((const unsigned char*)m)[idx] ? 1.0f : 0.0f;
    if (mode == 1) return ((const int*)m)[idx] ? 1.0f : 0.0f;
    return (((const float*)m)[idx] != 0.0f) ? 1.0f : 0.0f;
}

// ---------------- K0: sniff mask dtype ----------------
// mask[0,0,0..3] are guaranteed true (lengths >= 64), so word0 disambiguates:
// bytes -> 0x01010101, int32 -> 1, float32 -> 0x3F800000
__global__ void k_probe(const void* m) {
    unsigned int w = *(const unsigned int*)m;
    g_mask_mode = (w == 1u) ? 1 : ((w == 0x3F800000u) ? 2 : 0);
}

// ---------------- K1: M1 = Wq @ Wk^T ; M2 = Wv @ W_out ----------------
__global__ void k_precompute(const float* __restrict__ Wq, const float* __restrict__ Wk,
                             const float* __restrict__ Wv, const float* __restrict__ Wo) {
    extern __shared__ float sm[];
    int i = blockIdx.x, j = threadIdx.x;
    if (blockIdx.y == 0) {
        float* wks  = sm;               // [128][129] padded
        float* rowq = sm + 128 * 129;   // [128]
        for (int idx = j; idx < 128 * 128; idx += 128) {
            int rr = idx >> 7, cc = idx & 127;
            wks[rr * 129 + cc] = Wk[idx];
        }
        rowq[j] = Wq[i * 128 + j];
        __syncthreads();
        float acc = 0.f;
#pragma unroll 8
        for (int k = 0; k < 128; k++) acc += rowq[k] * wks[j * 129 + k];
        g_M1[i * 128 + j] = acc;
    } else {
        float* rowv = sm;
        rowv[j] = Wv[i * 128 + j];
        __syncthreads();
        float acc = 0.f;
#pragma unroll 8
        for (int k = 0; k < 128; k++) acc += rowv[k] * Wo[k * 128 + j];  // coalesced, L2-hot
        g_M2[i * 128 + j] = acc;
    }
}

// ---------------- K2a: diagonal tokens + seq + mask outputs ----------------
__global__ void k_diag(const float* __restrict__ vectors, const void* __restrict__ maskp,
                       const float* __restrict__ We, const float* __restrict__ be,
                       const float* __restrict__ g1, const float* __restrict__ b1,
                       float* __restrict__ out, int out_size) {
    int t = blockIdx.x, r = t >> 4, b = t & 15, d = threadIdx.x;
    __shared__ float v[8];
    __shared__ float red[8];
    __shared__ float sval;
    int mode = g_mask_mode;
    if (d < 8) v[d] = vectors[(((b * Tn + r) * Tn + r) << 3) + d];
    if (d == 0) sval = mask_at(maskp, (b * Tn + r) * Tn + r, mode);
    __syncthreads();
    float e = be[d];
#pragma unroll
    for (int i = 0; i < 8; i++) e += v[i] * We[i * 128 + d];
    float x = gelu_f(e) * sval;
    float s = x, q = x * x;
#pragma unroll
    for (int o = 16; o > 0; o >>= 1) {
        s += __shfl_xor_sync(0xffffffffu, s, o);
        q += __shfl_xor_sync(0xffffffffu, q, o);
    }
    if ((d & 31) == 0) { red[d >> 5] = s; red[4 + (d >> 5)] = q; }
    __syncthreads();
    s = red[0] + red[1] + red[2] + red[3];
    q = red[4] + red[5] + red[6] + red[7];
    float mu  = s * (1.0f / 128.0f);
    float var = q * (1.0f / 128.0f) - mu * mu;
    g_Xd[t * 128 + d] = (x - mu) * rsqrtf(var + 1e-5f) * g1[d] + b1[d];
    if (d == 0) {
        g_seq[t] = sval;
        if (out_size >= SEQ_OFF)       out[PAD_OFF + b * Tn + r] = (sval > 0.f) ? 0.f : 1.f;
        if (out_size >= GLB_OFF)       out[SEQ_OFF + t] = sval;
        if (out_size >= OUT_ALL && t < Tn) out[GLB_OFF + t] = 1.0f;
    }
}

// ---------------- K2b: Qp = Xd @ M1 * (1/sqrt(D)) ----------------
__global__ void k_qp() {
    extern __shared__ float sm[];
    float* M1s = sm;            // 16384
    float* xs  = sm + 16384;    // 32*128
    int d = threadIdx.x, t0 = blockIdx.x * 32;
    for (int idx = d; idx < 16384; idx += 128) M1s[idx] = g_M1[idx];
    for (int idx = d; idx < 32 * 128; idx += 128) xs[idx] = g_Xd[t0 * 128 + idx];
    __syncthreads();
    const float sc = 0.08838834764831845f;  // 1/sqrt(128)
    for (int g = 0; g < 8; g++) {
        float a0 = 0.f, a1 = 0.f, a2 = 0.f, a3 = 0.f;
        int base = (g * 4) * 128;
#pragma unroll 8
        for (int e = 0; e < 128; e++) {
            float m = M1s[e * 128 + d];
            a0 += xs[base + e] * m;
            a1 += xs[base + 128 + e] * m;
            a2 += xs[base + 256 + e] * m;
            a3 += xs[base + 384 + e] * m;
        }
        g_Qp[(t0 + g * 4 + 0) * 128 + d] = a0 * sc;
        g_Qp[(t0 + g * 4 + 1) * 128 + d] = a1 * sc;
        g_Qp[(t0 + g * 4 + 2) * 128 + d] = a2 * sc;
        g_Qp[(t0 + g * 4 + 3) * 128 + d] = a3 * sc;
    }
}

// ---------------- K3: fused embed+LN+attention per (r,b) ----------------
// smem floats: xs 128*129, vbuf 1024, qps 128, mrow 128, ws 128, red 8
#define K3_SMEM ((128*129 + 1024 + 128 + 128 + 128 + 8) * 4)
__global__ void __launch_bounds__(128) k_attn(
    const float* __restrict__ vectors, const void* __restrict__ maskp,
    const float* __restrict__ We, const float* __restrict__ be,
    const float* __restrict__ g1, const float* __restrict__ b1) {
    extern __shared__ float sm[];
    float* xs   = sm;                  // [128][129] padded -> conflict-free both axes
    float* vbuf = xs + 128 * 129;      // 128 c * 8 inputs (contiguous in gmem)
    float* qps  = vbuf + 1024;
    float* mrow = qps + 128;
    float* ws   = mrow + 128;
    float* red  = ws + 128;

    int t = blockIdx.x, r = t >> 4, b = t & 15, tid = threadIdx.x;
    int lane = tid & 31, w = tid >> 5;
    int mode = g_mask_mode;

    const float* vsrc = vectors + (size_t)(b * Tn + r) * (Tn * In);
    for (int i = tid; i < Tn * In; i += 128) vbuf[i] = vsrc[i];
    mrow[tid] = mask_at(maskp, (b * Tn + r) * Tn + tid, mode);
    qps[tid]  = g_Qp[t * 128 + tid];

    float wcol[8];
#pragma unroll
    for (int i = 0; i < 8; i++) wcol[i] = We[i * 128 + tid];
    float bed = be[tid];
    __syncthreads();

    // Phase A: pre-LN x[c][d] = gelu(v_c @ We + be) * mask
    for (int c = 0; c < 128; c++) {
        const float* vc = vbuf + c * 8;
        float e = bed;
#pragma unroll
        for (int i = 0; i < 8; i++) e += vc[i] * wcol[i];
        xs[c * 129 + tid] = gelu_f(e) * mrow[c];
    }
    __syncthreads();

    // LN pass: warp per row c
    {
        float g1r0 = g1[lane], g1r1 = g1[lane + 32], g1r2 = g1[lane + 64], g1r3 = g1[lane + 96];
        float b1r0 = b1[lane], b1r1 = b1[lane + 32], b1r2 = b1[lane + 64], b1r3 = b1[lane + 96];
        for (int c = w; c < 128; c += 4) {
            float* row = xs + c * 129;
            float v0 = row[lane], v1 = row[lane + 32], v2 = row[lane + 64], v3 = row[lane + 96];
            float s = v0 + v1 + v2 + v3;
            float q = v0 * v0 + v1 * v1 + v2 * v2 + v3 * v3;
#pragma unroll
            for (int o = 16; o > 0; o >>= 1) {
                s += __shfl_xor_sync(0xffffffffu, s, o);
                q += __shfl_xor_sync(0xffffffffu, q, o);
            }
            float mu  = s * (1.0f / 128.0f);
            float var = q * (1.0f / 128.0f) - mu * mu;
            float rstd = rsqrtf(var + 1e-5f);
            row[lane]      = (v0 - mu) * rstd * g1r0 + b1r0;
            row[lane + 32] = (v1 - mu) * rstd * g1r1 + b1r1;
            row[lane + 64] = (v2 - mu) * rstd * g1r2 + b1r2;
            row[lane + 96] = (v3 - mu) * rstd * g1r3 + b1r3;
        }
    }
    __syncthreads();

    // Phase B: logits (thread c), softmax across block
    {
        int c = tid;
        const float* row = xs + c * 129;
        float acc = 0.f;
#pragma unroll 8
        for (int dd = 0; dd < 128; dd++) acc += row[dd] * qps[dd];
        bool am = (mrow[c] > 0.f) || (c == r);
        float logit = acc + (am ? 0.f : -1e9f);

        float mx = logit;
#pragma unroll
        for (int o = 16; o > 0; o >>= 1) mx = fmaxf(mx, __shfl_xor_sync(0xffffffffu, mx, o));
        if (lane == 0) red[w] = mx;
        __syncthreads();
        mx = fmaxf(fmaxf(red[0], red[1]), fmaxf(red[2], red[3]));

        float p = __expf(logit - mx);
        float sum = p;
#pragma unroll
        for (int o = 16; o > 0; o >>= 1) sum += __shfl_xor_sync(0xffffffffu, sum, o);
        __syncthreads();
        if (lane == 0) red[w] = sum;
        __syncthreads();
        sum = red[0] + red[1] + red[2] + red[3];
        ws[c] = p * __frcp_rn(sum);
    }
    __syncthreads();

    // Phase C: y[d] = sum_c w_c * x[c][d]
    {
        float y = 0.f;
#pragma unroll 8
        for (int c = 0; c < 128; c++) y += ws[c] * xs[c * 129 + tid];
        g_Y[t * 128 + tid] = y;
    }
}

// ---------------- K4: Emb = Y@Wv, Hp = Y@M2, out = LN(gelu(Hp+bo)+Emb)*seq ----------------
// smem floats: WvS 16384, M2S 16384, ys 2048, zs 16*129
#define K4_SMEM ((16384 + 16384 + 2048 + 16*129) * 4)
__global__ void __launch_bounds__(128) k_out(
    const float* __restrict__ Wv, const float* __restrict__ bo,
    const float* __restrict__ g2, const float* __restrict__ b2,
    float* __restrict__ out, int out_size) {
    extern __shared__ float sm[];
    float* WvS = sm;
    float* M2S = WvS + 16384;
    float* ys  = M2S + 16384;
    float* zs  = ys + 2048;
    int tid = threadIdx.x, t0 = blockIdx.x * 16;
    int lane = tid & 31, w = tid >> 5;

    for (int i = tid; i < 16384; i += 128) { WvS[i] = Wv[i]; M2S[i] = g_M2[i]; }
    for (int i = tid; i < 2048; i += 128) ys[i] = g_Y[t0 * 128 + i];
    __syncthreads();

    float accE[16], accH[16];
#pragma unroll
    for (int tt = 0; tt < 16; tt++) { accE[tt] = 0.f; accH[tt] = 0.f; }
    for (int e = 0; e < 128; e++) {
        float wv = WvS[e * 128 + tid];
        float m2 = M2S[e * 128 + tid];
#pragma unroll
        for (int tt = 0; tt < 16; tt++) {
            float ye = ys[tt * 128 + e];  // smem broadcast
            accE[tt] += ye * wv;
            accH[tt] += ye * m2;
        }
    }
    float bod = bo[tid];
#pragma unroll
    for (int tt = 0; tt < 16; tt++) {
        float h = gelu_f(accH[tt] + bod);
        zs[tt * 129 + tid] = h + accE[tt];  // residual
    }
    __syncthreads();

    if (out_size >= EMB_SZ) {
        float g2r0 = g2[lane], g2r1 = g2[lane + 32], g2r2 = g2[lane + 64], g2r3 = g2[lane + 96];
        float b2r0 = b2[lane], b2r1 = b2[lane + 32], b2r2 = b2[lane + 64], b2r3 = b2[lane + 96];
        for (int tt = w; tt < 16; tt += 4) {
            float* row = zs + tt * 129;
            float v0 = row[lane], v1 = row[lane + 32], v2 = row[lane + 64], v3 = row[lane + 96];
            float s = v0 + v1 + v2 + v3;
            float q = v0 * v0 + v1 * v1 + v2 * v2 + v3 * v3;
#pragma unroll
            for (int o = 16; o > 0; o >>= 1) {
                s += __shfl_xor_sync(0xffffffffu, s, o);
                q += __shfl_xor_sync(0xffffffffu, q, o);
            }
            float mu  = s * (1.0f / 128.0f);
            float var = q * (1.0f / 128.0f) - mu * mu;
            float rstd = rsqrtf(var + 1e-5f);
            float sf = g_seq[t0 + tt];
            int ob = (t0 + tt) * 128;
            out[ob + lane]      = ((v0 - mu) * rstd * g2r0 + b2r0) * sf;
            out[ob + lane + 32] = ((v1 - mu) * rstd * g2r1 + b2r1) * sf;
            out[ob + lane + 64] = ((v2 - mu) * rstd * g2r2 + b2r2) * sf;
            out[ob + lane + 96] = ((v3 - mu) * rstd * g2r3 + b2r3) * sf;
        }
    }
}

// ---------------- launch ----------------
extern "C" void kernel_launch(void* const* d_in, const int* in_sizes, int n_in,
                              void* d_out, int out_size) {
    const float* vectors = (const float*)d_in[0];
    const void*  maskp   = d_in[1];
    const float* We = (const float*)d_in[2];
    const float* be = (const float*)d_in[3];
    const float* g1 = (const float*)d_in[4];
    const float* b1 = (const float*)d_in[5];
    const float* Wq = (const float*)d_in[6];
    const float* Wk = (const float*)d_in[7];
    const float* Wv = (const float*)d_in[8];
    const float* Wo = (const float*)d_in[9];
    const float* bo = (const float*)d_in[10];
    const float* g2 = (const float*)d_in[11];
    const float* b2 = (const float*)d_in[12];
    float* out = (float*)d_out;

    int pre_smem = (128 * 129 + 128) * 4;
    int qp_smem  = (16384 + 32 * 128) * 4;
    cudaFuncSetAttribute(k_precompute, cudaFuncAttributeMaxDynamicSharedMemorySize, pre_smem);
    cudaFuncSetAttribute(k_qp,         cudaFuncAttributeMaxDynamicSharedMemorySize, qp_smem);
    cudaFuncSetAttribute(k_attn,       cudaFuncAttributeMaxDynamicSharedMemorySize, K3_SMEM);
    cudaFuncSetAttribute(k_out,        cudaFuncAttributeMaxDynamicSharedMemorySize, K4_SMEM);

    k_probe<<<1, 1>>>(maskp);
    k_precompute<<<dim3(128, 2), 128, pre_smem>>>(Wq, Wk, Wv, Wo);
    k_diag<<<NT, 128>>>(vectors, maskp, We, be, g1, b1, out, out_size);
    k_qp<<<NT / 32, 128, qp_smem>>>();
    k_attn<<<NT, 128, K3_SMEM>>>(vectors, maskp, We, be, g1, b1);
    k_out<<<NT / 16, 128, K4_SMEM>>>(Wv, bo, g2, b2, out, out_size);
}

// round 3
// speedup vs baseline: 1.2695x; 1.2695x over previous
#include <cuda_runtime.h>
#include <cuda_bf16.h>

// Shapes
#define Bn 16
#define Tn 128
#define In 8
#define Dn 128
#define NT 2048           // Tn * Bn tokens, t = r*16 + b

// Output packing (fp32 concat of the reference tuple)
#define EMB_SZ   (NT*Dn)        // 262144
#define PAD_OFF  (EMB_SZ)       // padding_mask (B,T)
#define SEQ_OFF  (PAD_OFF+2048) // sequence_mask (T,B,1)
#define GLB_OFF  (SEQ_OFF+2048) // global_mask (T)
#define OUT_ALL  (GLB_OFF+128)  // 266368

// ---------------- scratch (device globals: allocation-free) ----------------
__device__ float g_M1[Dn*Dn];   // Wq @ Wk^T
__device__ float g_M2[Dn*Dn];   // Wv @ W_out
__device__ float g_Qp[NT*Dn];   // LN(diag-x) @ M1 / sqrt(D)
__device__ float g_Y [NT*Dn];   // softmax-weighted sum of x rows
__device__ float g_seq[NT];     // seq[r,b] as 0/1
__device__ int   g_mask_mode;   // 0=byte, 1=int32, 2=float32

// ---------------- helpers ----------------
__device__ __forceinline__ float gelu_f(float x) {
    // tanh-form gelu == x * sigmoid(2*0.79788456*(x + 0.044715 x^3)); 2 MUFU
    float u2 = 1.5957691216057308f * fmaf(0.044715f * x, x * x, x);
    return __fdividef(x, 1.0f + __expf(-u2));
}

__device__ __forceinline__ float mask_at(const void* m, int idx, int mode) {
    if (mode == 0) return ((const unsigned char*)m)[idx] ? 1.0f : 0.0f;
    if (mode == 1) return ((const int*)m)[idx] ? 1.0f : 0.0f;
    return (((const float*)m)[idx] != 0.0f) ? 1.0f : 0.0f;
}

// ---------------- K1: probe + M1 = Wq @ Wk^T ; M2 = Wv @ W_out ----------------
__global__ void k_precompute(const float* __restrict__ Wq, const float* __restrict__ Wk,
                             const float* __restrict__ Wv, const float* __restrict__ Wo,
                             const void* __restrict__ maskp) {
    extern __shared__ float sm[];
    int i = blockIdx.x, j = threadIdx.x;
    if (blockIdx.y == 0) {
        if (i == 0 && j == 0) {
            // mask[0,0,0..3] are true (lengths >= T/2): word disambiguates dtype
            unsigned int w = *(const unsigned int*)maskp;
            g_mask_mode = (w == 1u) ? 1 : ((w == 0x3F800000u) ? 2 : 0);
        }
        float* wks  = sm;               // [128][129] padded
        float* rowq = sm + 128 * 129;   // [128]
        for (int idx = j; idx < 128 * 128; idx += 128) {
            int rr = idx >> 7, cc = idx & 127;
            wks[rr * 129 + cc] = Wk[idx];
        }
        rowq[j] = Wq[i * 128 + j];
        __syncthreads();
        float acc = 0.f;
#pragma unroll 8
        for (int k = 0; k < 128; k++) acc += rowq[k] * wks[j * 129 + k];
        g_M1[i * 128 + j] = acc;
    } else {
        float* rowv = sm;
        rowv[j] = Wv[i * 128 + j];
        __syncthreads();
        float acc = 0.f;
#pragma unroll 8
        for (int k = 0; k < 128; k++) acc += rowv[k] * Wo[k * 128 + j];
        g_M2[i * 128 + j] = acc;
    }
}

// ---------------- K2: diag tokens -> LN -> Qp, + mask outputs ----------------
// grid = 128 (one block per r), block = 128, 16 tokens (b=0..15) per block
__global__ void __launch_bounds__(128) k_pre(
    const float* __restrict__ vectors, const void* __restrict__ maskp,
    const float* __restrict__ We, const float* __restrict__ be,
    const float* __restrict__ g1, const float* __restrict__ b1,
    float* __restrict__ out, int out_size) {
    __shared__ float vs[16 * 8];
    __shared__ float mval[16];
    __shared__ float xds[16 * 128];
    int r = blockIdx.x, tid = threadIdx.x;
    int lane = tid & 31, w = tid >> 5;
    int mode = g_mask_mode;

    { // load 16 diagonal input vectors + diag mask values
        int tt = tid >> 3, i = tid & 7;  // tt = b
        vs[tid] = vectors[((((tt * Tn + r) * Tn) + r) << 3) + i];
        if (tid < 16) mval[tid] = mask_at(maskp, (tid * Tn + r) * Tn + r, mode);
    }
    float wcol[8];
#pragma unroll
    for (int i = 0; i < 8; i++) wcol[i] = We[i * 128 + tid];
    float bed = be[tid];
    __syncthreads();

    // embed + gelu + mask, thread = dim d, 16 tokens
#pragma unroll
    for (int tt = 0; tt < 16; tt++) {
        float e = bed;
#pragma unroll
        for (int i = 0; i < 8; i++) e += vs[tt * 8 + i] * wcol[i];
        xds[tt * 128 + tid] = gelu_f(e) * mval[tt];
    }
    __syncthreads();

    // LN: warp per row, 4 rounds
    {
        float g1r0 = g1[lane], g1r1 = g1[lane + 32], g1r2 = g1[lane + 64], g1r3 = g1[lane + 96];
        float b1r0 = b1[lane], b1r1 = b1[lane + 32], b1r2 = b1[lane + 64], b1r3 = b1[lane + 96];
        for (int tt = w; tt < 16; tt += 4) {
            float* row = xds + tt * 128;
            float v0 = row[lane], v1 = row[lane + 32], v2 = row[lane + 64], v3 = row[lane + 96];
            float s = v0 + v1 + v2 + v3;
            float q = v0 * v0 + v1 * v1 + v2 * v2 + v3 * v3;
#pragma unroll
            for (int o = 16; o > 0; o >>= 1) {
                s += __shfl_xor_sync(0xffffffffu, s, o);
                q += __shfl_xor_sync(0xffffffffu, q, o);
            }
            float mu  = s * (1.0f / 128.0f);
            float var = q * (1.0f / 128.0f) - mu * mu;
            float rstd = rsqrtf(var + 1e-5f);
            row[lane]      = (v0 - mu) * rstd * g1r0 + b1r0;
            row[lane + 32] = (v1 - mu) * rstd * g1r1 + b1r1;
            row[lane + 64] = (v2 - mu) * rstd * g1r2 + b1r2;
            row[lane + 96] = (v3 - mu) * rstd * g1r3 + b1r3;
        }
    }
    __syncthreads();

    // Qp = Xd @ M1 * 1/sqrt(D): 16 accumulator chains, M1 streamed from L2
    float acc[16];
#pragma unroll
    for (int tt = 0; tt < 16; tt++) acc[tt] = 0.f;
#pragma unroll 4
    for (int e = 0; e < 128; e++) {
        float m = __ldg(&g_M1[e * 128 + tid]);
#pragma unroll
        for (int tt = 0; tt < 16; tt++) acc[tt] += xds[tt * 128 + e] * m;
    }
    const float sc = 0.08838834764831845f;  // 1/sqrt(128)
#pragma unroll
    for (int tt = 0; tt < 16; tt++) g_Qp[((r << 4) + tt) * 128 + tid] = acc[tt] * sc;

    // masks / seq outputs
    if (tid < 16) {
        float sval = mval[tid];
        g_seq[(r << 4) + tid] = sval;
        if (out_size >= SEQ_OFF) out[PAD_OFF + tid * Tn + r] = (sval > 0.f) ? 0.f : 1.f;
        if (out_size >= GLB_OFF) out[SEQ_OFF + (r << 4) + tid] = sval;
    }
    if (tid == 0 && out_size >= OUT_ALL) out[GLB_OFF + r] = 1.0f;
}

// ---------------- K3: fused embed+LN+attention per (r,b) ----------------
// smem floats: xs 128*129, vbuf 1024, qps 128, mrow 128, ws 128, red 8
#define K3_SMEM ((128*129 + 1024 + 128 + 128 + 128 + 8) * 4)
__global__ void __launch_bounds__(128) k_attn(
    const float* __restrict__ vectors, const void* __restrict__ maskp,
    const float* __restrict__ We, const float* __restrict__ be,
    const float* __restrict__ g1, const float* __restrict__ b1) {
    extern __shared__ float sm[];
    float* xs   = sm;                  // [128][129] padded
    float* vbuf = xs + 128 * 129;      // 128 c * 8 inputs (16B aligned: 66048 % 16 == 0)
    float* qps  = vbuf + 1024;
    float* mrow = qps + 128;
    float* ws   = mrow + 128;
    float* red  = ws + 128;

    int t = blockIdx.x, r = t >> 4, b = t & 15, tid = threadIdx.x;
    int lane = tid & 31, w = tid >> 5;
    int mode = g_mask_mode;

    { // float4 tile load: 1024 contiguous floats
        const float4* vsrc4 = (const float4*)(vectors + (size_t)(b * Tn + r) * (Tn * In));
        float4* vb4 = (float4*)vbuf;
        vb4[tid] = vsrc4[tid];
        vb4[tid + 128] = vsrc4[tid + 128];
    }
    mrow[tid] = mask_at(maskp, (b * Tn + r) * Tn + tid, mode);
    qps[tid]  = g_Qp[t * 128 + tid];

    float wcol[8];
#pragma unroll
    for (int i = 0; i < 8; i++) wcol[i] = We[i * 128 + tid];
    float bed = be[tid];
    __syncthreads();

    // Phase A: pre-LN x[c][d] = gelu(v_c @ We + be) * mask, 2 rows per iter
    {
        const float4* vb4 = (const float4*)vbuf;
        for (int c = 0; c < 128; c += 2) {
            float4 a0 = vb4[2 * c],     a1 = vb4[2 * c + 1];
            float4 c0 = vb4[2 * c + 2], c1 = vb4[2 * c + 3];
            float e0 = bed, e1 = bed;
            e0 += a0.x * wcol[0]; e1 += c0.x * wcol[0];
            e0 += a0.y * wcol[1]; e1 += c0.y * wcol[1];
            e0 += a0.z * wcol[2]; e1 += c0.z * wcol[2];
            e0 += a0.w * wcol[3]; e1 += c0.w * wcol[3];
            e0 += a1.x * wcol[4]; e1 += c1.x * wcol[4];
            e0 += a1.y * wcol[5]; e1 += c1.y * wcol[5];
            e0 += a1.z * wcol[6]; e1 += c1.z * wcol[6];
            e0 += a1.w * wcol[7]; e1 += c1.w * wcol[7];
            xs[c * 129 + tid]       = gelu_f(e0) * mrow[c];
            xs[(c + 1) * 129 + tid] = gelu_f(e1) * mrow[c + 1];
        }
    }
    __syncthreads();

    // LN pass: warp per row c
    {
        float g1r0 = g1[lane], g1r1 = g1[lane + 32], g1r2 = g1[lane + 64], g1r3 = g1[lane + 96];
        float b1r0 = b1[lane], b1r1 = b1[lane + 32], b1r2 = b1[lane + 64], b1r3 = b1[lane + 96];
        for (int c = w; c < 128; c += 4) {
            float* row = xs + c * 129;
            float v0 = row[lane], v1 = row[lane + 32], v2 = row[lane + 64], v3 = row[lane + 96];
            float s = v0 + v1 + v2 + v3;
            float q = v0 * v0 + v1 * v1 + v2 * v2 + v3 * v3;
#pragma unroll
            for (int o = 16; o > 0; o >>= 1) {
                s += __shfl_xor_sync(0xffffffffu, s, o);
                q += __shfl_xor_sync(0xffffffffu, q, o);
            }
            float mu  = s * (1.0f / 128.0f);
            float var = q * (1.0f / 128.0f) - mu * mu;
            float rstd = rsqrtf(var + 1e-5f);
            row[lane]      = (v0 - mu) * rstd * g1r0 + b1r0;
            row[lane + 32] = (v1 - mu) * rstd * g1r1 + b1r1;
            row[lane + 64] = (v2 - mu) * rstd * g1r2 + b1r2;
            row[lane + 96] = (v3 - mu) * rstd * g1r3 + b1r3;
        }
    }
    __syncthreads();

    // Phase B: logits (thread c), softmax across block
    {
        int c = tid;
        const float* row = xs + c * 129;
        float acc = 0.f;
#pragma unroll 8
        for (int dd = 0; dd < 128; dd++) acc += row[dd] * qps[dd];
        bool am = (mrow[c] > 0.f) || (c == r);
        float logit = acc + (am ? 0.f : -1e9f);

        float mx = logit;
#pragma unroll
        for (int o = 16; o > 0; o >>= 1) mx = fmaxf(mx, __shfl_xor_sync(0xffffffffu, mx, o));
        if (lane == 0) red[w] = mx;
        __syncthreads();
        mx = fmaxf(fmaxf(red[0], red[1]), fmaxf(red[2], red[3]));

        float p = __expf(logit - mx);
        float sum = p;
#pragma unroll
        for (int o = 16; o > 0; o >>= 1) sum += __shfl_xor_sync(0xffffffffu, sum, o);
        __syncthreads();
        if (lane == 0) red[w] = sum;
        __syncthreads();
        sum = red[0] + red[1] + red[2] + red[3];
        ws[c] = p * __frcp_rn(sum);
    }
    __syncthreads();

    // Phase C: y[d] = sum_c w_c * x[c][d]
    {
        float y = 0.f;
#pragma unroll 8
        for (int c = 0; c < 128; c++) y += ws[c] * xs[c * 129 + tid];
        g_Y[t * 128 + tid] = y;
    }
}

// ---------------- K4: Emb = Y@Wv, Hp = Y@M2, out = LN(gelu(Hp+bo)+Emb)*seq ----------------
// grid = 128, block = 256 (half 0: E = Y@Wv, half 1: H = Y@M2), 16 tokens/block
__global__ void __launch_bounds__(256) k_out(
    const float* __restrict__ Wv, const float* __restrict__ bo,
    const float* __restrict__ g2, const float* __restrict__ b2,
    float* __restrict__ out, int out_size) {
    __shared__ float ys[2048];
    __shared__ float zsE[16 * 128];
    __shared__ float zs[16 * 129];
    int tid = threadIdx.x, t0 = blockIdx.x * 16;
    int d = tid & 127, half = tid >> 7;
    int lane = tid & 31, w = tid >> 5;

    { // stage Y tile (float4)
        const float4* Y4 = (const float4*)(g_Y + t0 * 128);
        float4* y4 = (float4*)ys;
        y4[tid] = Y4[tid];
        y4[tid + 256] = Y4[tid + 256];
    }
    __syncthreads();

    const float* W = half ? g_M2 : Wv;   // each half owns one weight matrix (L2-hot)
    float acc[16];
#pragma unroll
    for (int tt = 0; tt < 16; tt++) acc[tt] = 0.f;
#pragma unroll 4
    for (int e = 0; e < 128; e++) {
        float m = __ldg(&W[e * 128 + d]);
#pragma unroll
        for (int tt = 0; tt < 16; tt++) acc[tt] += ys[tt * 128 + e] * m;
    }
    if (half == 0) {
#pragma unroll
        for (int tt = 0; tt < 16; tt++) zsE[tt * 128 + d] = acc[tt];
    }
    __syncthreads();
    if (half == 1) {
        float bod = bo[d];
#pragma unroll
        for (int tt = 0; tt < 16; tt++)
            zs[tt * 129 + d] = gelu_f(acc[tt] + bod) + zsE[tt * 128 + d];
    }
    __syncthreads();

    if (out_size >= EMB_SZ) {
        float g2r0 = g2[lane], g2r1 = g2[lane + 32], g2r2 = g2[lane + 64], g2r3 = g2[lane + 96];
        float b2r0 = b2[lane], b2r1 = b2[lane + 32], b2r2 = b2[lane + 64], b2r3 = b2[lane + 96];
        for (int tt = w; tt < 16; tt += 8) {   // 8 warps, 16 rows
            float* row = zs + tt * 129;
            float v0 = row[lane], v1 = row[lane + 32], v2 = row[lane + 64], v3 = row[lane + 96];
            float s = v0 + v1 + v2 + v3;
            float q = v0 * v0 + v1 * v1 + v2 * v2 + v3 * v3;
#pragma unroll
            for (int o = 16; o > 0; o >>= 1) {
                s += __shfl_xor_sync(0xffffffffu, s, o);
                q += __shfl_xor_sync(0xffffffffu, q, o);
            }
            float mu  = s * (1.0f / 128.0f);
            float var = q * (1.0f / 128.0f) - mu * mu;
            float rstd = rsqrtf(var + 1e-5f);
            float sf = g_seq[t0 + tt];
            int ob = (t0 + tt) * 128;
            out[ob + lane]      = ((v0 - mu) * rstd * g2r0 + b2r0) * sf;
            out[ob + lane + 32] = ((v1 - mu) * rstd * g2r1 + b2r1) * sf;
            out[ob + lane + 64] = ((v2 - mu) * rstd * g2r2 + b2r2) * sf;
            out[ob + lane + 96] = ((v3 - mu) * rstd * g2r3 + b2r3) * sf;
        }
    }
}

// ---------------- launch ----------------
extern "C" void kernel_launch(void* const* d_in, const int* in_sizes, int n_in,
                              void* d_out, int out_size) {
    const float* vectors = (const float*)d_in[0];
    const void*  maskp   = d_in[1];
    const float* We = (const float*)d_in[2];
    const float* be = (const float*)d_in[3];
    const float* g1 = (const float*)d_in[4];
    const float* b1 = (const float*)d_in[5];
    const float* Wq = (const float*)d_in[6];
    const float* Wk = (const float*)d_in[7];
    const float* Wv = (const float*)d_in[8];
    const float* Wo = (const float*)d_in[9];
    const float* bo = (const float*)d_in[10];
    const float* g2 = (const float*)d_in[11];
    const float* b2 = (const float*)d_in[12];
    float* out = (float*)d_out;

    int pre_smem = (128 * 129 + 128) * 4;
    cudaFuncSetAttribute(k_precompute, cudaFuncAttributeMaxDynamicSharedMemorySize, pre_smem);
    cudaFuncSetAttribute(k_attn,       cudaFuncAttributeMaxDynamicSharedMemorySize, K3_SMEM);

    k_precompute<<<dim3(128, 2), 128, pre_smem>>>(Wq, Wk, Wv, Wo, maskp);
    k_pre<<<128, 128>>>(vectors, maskp, We, be, g1, b1, out, out_size);
    k_attn<<<NT, 128, K3_SMEM>>>(vectors, maskp, We, be, g1, b1);
    k_out<<<128, 256>>>(Wv, bo, g2, b2, out, out_size);
}

// round 4
// speedup vs baseline: 1.6531x; 1.3022x over previous
#include <cuda_runtime.h>
#include <cuda_bf16.h>

// Shapes
#define Bn 16
#define Tn 128
#define In 8
#define Dn 128
#define NT 2048           // Tn * Bn tokens, t = r*16 + b

// Output packing (fp32 concat of the reference tuple)
#define EMB_SZ   (NT*Dn)        // 262144
#define PAD_OFF  (EMB_SZ)       // padding_mask (B,T)
#define SEQ_OFF  (PAD_OFF+2048) // sequence_mask (T,B,1)
#define GLB_OFF  (SEQ_OFF+2048) // global_mask (T)
#define OUT_ALL  (GLB_OFF+128)  // 266368

// ---------------- scratch (device globals: allocation-free) ----------------
__device__ __align__(16) float g_M1[Dn*Dn];   // Wq @ Wk^T
__device__ __align__(16) float g_M2[Dn*Dn];   // Wv @ W_out
__device__ __align__(16) float g_Qp[NT*Dn];   // LN(diag-x) @ M1 / sqrt(D)
__device__ __align__(16) float g_Y [NT*Dn];   // softmax-weighted LN-combined rows
__device__ float g_seq[NT];     // seq[r,b] as 0/1
__device__ int   g_mask_mode;   // 0=byte, 1=int32, 2=float32

// ---------------- helpers ----------------
__device__ __forceinline__ float gelu_f(float x) {
    // tanh-form gelu == x * sigmoid(2*0.79788456*(x + 0.044715 x^3))
    float u2 = 1.5957691216057308f * fmaf(0.044715f * x, x * x, x);
    return __fdividef(x, 1.0f + __expf(-u2));
}

__device__ __forceinline__ float mask_at(const void* m, int idx, int mode) {
    if (mode == 0) return ((const unsigned char*)m)[idx] ? 1.0f : 0.0f;
    if (mode == 1) return ((const int*)m)[idx] ? 1.0f : 0.0f;
    return (((const float*)m)[idx] != 0.0f) ? 1.0f : 0.0f;
}

// ---------------- K1: probe + M1 = Wq @ Wk^T ; M2 = Wv @ W_out ----------------
__global__ void k_precompute(const float* __restrict__ Wq, const float* __restrict__ Wk,
                             const float* __restrict__ Wv, const float* __restrict__ Wo,
                             const void* __restrict__ maskp) {
    extern __shared__ float sm[];
    int i = blockIdx.x, j = threadIdx.x;
    if (blockIdx.y == 0) {
        if (i == 0 && j == 0) {
            unsigned int w = *(const unsigned int*)maskp;
            g_mask_mode = (w == 1u) ? 1 : ((w == 0x3F800000u) ? 2 : 0);
        }
        float* wks  = sm;               // [128][129] padded
        float* rowq = sm + 128 * 129;   // [128]
        for (int idx = j; idx < 128 * 128; idx += 128) {
            int rr = idx >> 7, cc = idx & 127;
            wks[rr * 129 + cc] = Wk[idx];
        }
        rowq[j] = Wq[i * 128 + j];
        __syncthreads();
        float acc = 0.f;
#pragma unroll 8
        for (int k = 0; k < 128; k++) acc += rowq[k] * wks[j * 129 + k];
        g_M1[i * 128 + j] = acc;
    } else {
        float* rowv = sm;
        rowv[j] = Wv[i * 128 + j];
        __syncthreads();
        float acc = 0.f;
#pragma unroll 8
        for (int k = 0; k < 128; k++) acc += rowv[k] * Wo[k * 128 + j];
        g_M2[i * 128 + j] = acc;
    }
}

// ---------------- K2: diag tokens -> LN -> Qp, + mask outputs ----------------
// grid = 256 (blk -> r = blk>>1, 8 tokens), block = 128
__global__ void __launch_bounds__(128) k_pre(
    const float* __restrict__ vectors, const void* __restrict__ maskp,
    const float* __restrict__ We, const float* __restrict__ be,
    const float* __restrict__ g1, const float* __restrict__ b1,
    float* __restrict__ out, int out_size) {
    __shared__ float vs[64];
    __shared__ float mval[8];
    __shared__ float xds[8 * 128];
    int r = blockIdx.x >> 1, bb = (blockIdx.x & 1) << 3;
    int tid = threadIdx.x, lane = tid & 31, w = tid >> 5;
    int mode = g_mask_mode;

    if (tid < 64) {
        int tt = tid >> 3, i = tid & 7;
        vs[tid] = vectors[(((((bb + tt) * Tn + r) * Tn) + r) << 3) + i];
    }
    if (tid < 8) mval[tid] = mask_at(maskp, ((bb + tid) * Tn + r) * Tn + r, mode);
    float wcol[8];
#pragma unroll
    for (int i = 0; i < 8; i++) wcol[i] = We[i * 128 + tid];
    float bed = be[tid];
    __syncthreads();

#pragma unroll
    for (int tt = 0; tt < 8; tt++) {
        float e = bed;
#pragma unroll
        for (int i = 0; i < 8; i++) e = fmaf(vs[tt * 8 + i], wcol[i], e);
        xds[tt * 128 + tid] = gelu_f(e) * mval[tt];
    }
    __syncthreads();

    // LN: warp per token row (4 warps x 2 tokens)
    {
        float g1r0 = g1[lane], g1r1 = g1[lane + 32], g1r2 = g1[lane + 64], g1r3 = g1[lane + 96];
        float b1r0 = b1[lane], b1r1 = b1[lane + 32], b1r2 = b1[lane + 64], b1r3 = b1[lane + 96];
        for (int tt = w; tt < 8; tt += 4) {
            float* row = xds + tt * 128;
            float v0 = row[lane], v1 = row[lane + 32], v2 = row[lane + 64], v3 = row[lane + 96];
            float s = v0 + v1 + v2 + v3;
            float q = v0 * v0 + v1 * v1 + v2 * v2 + v3 * v3;
#pragma unroll
            for (int o = 16; o > 0; o >>= 1) {
                s += __shfl_xor_sync(0xffffffffu, s, o);
                q += __shfl_xor_sync(0xffffffffu, q, o);
            }
            float mu  = s * (1.0f / 128.0f);
            float var = q * (1.0f / 128.0f) - mu * mu;
            float rstd = rsqrtf(var + 1e-5f);
            row[lane]      = (v0 - mu) * rstd * g1r0 + b1r0;
            row[lane + 32] = (v1 - mu) * rstd * g1r1 + b1r1;
            row[lane + 64] = (v2 - mu) * rstd * g1r2 + b1r2;
            row[lane + 96] = (v3 - mu) * rstd * g1r3 + b1r3;
        }
    }
    __syncthreads();

    // Qp = Xd @ M1 * 1/sqrt(D): register-tiled, thread = 4 d x 2 tokens
    {
        int dg = tid & 31, tg = tid >> 5;
        const float4* M14 = (const float4*)g_M1;
        const float* yA = xds + (tg * 2) * 128;
        const float* yB = xds + (tg * 2 + 1) * 128;
        float a0 = 0, a1 = 0, a2 = 0, a3 = 0, c0 = 0, c1 = 0, c2 = 0, c3 = 0;
#pragma unroll 8
        for (int e = 0; e < 128; e++) {
            float4 m = M14[e * 32 + dg];
            float ya = yA[e], yb = yB[e];
            a0 = fmaf(ya, m.x, a0); a1 = fmaf(ya, m.y, a1);
            a2 = fmaf(ya, m.z, a2); a3 = fmaf(ya, m.w, a3);
            c0 = fmaf(yb, m.x, c0); c1 = fmaf(yb, m.y, c1);
            c2 = fmaf(yb, m.z, c2); c3 = fmaf(yb, m.w, c3);
        }
        const float sc = 0.08838834764831845f;  // 1/sqrt(128)
        int tokA = (r << 4) + bb + tg * 2;
        float4* Qp4 = (float4*)g_Qp;
        Qp4[tokA * 32 + dg]       = make_float4(a0 * sc, a1 * sc, a2 * sc, a3 * sc);
        Qp4[(tokA + 1) * 32 + dg] = make_float4(c0 * sc, c1 * sc, c2 * sc, c3 * sc);
    }

    if (tid < 8) {
        float sval = mval[tid];
        int t = (r << 4) + bb + tid;
        g_seq[t] = sval;
        if (out_size >= SEQ_OFF) out[PAD_OFF + (bb + tid) * Tn + r] = (sval > 0.f) ? 0.f : 1.f;
        if (out_size >= GLB_OFF) out[SEQ_OFF + t] = sval;
    }
    if (tid == 0 && bb == 0 && out_size >= OUT_ALL) out[GLB_OFF + r] = 1.0f;
}

// ---------------- K3: fused embed+attention, LN algebraically folded ----------------
// smem floats: xs 128*132, vbuf 1024, qg 128, As 128, red 16
#define XS_F   (128*132)
#define K3_SMEM ((XS_F + 1024 + 128 + 128 + 16) * 4)
__global__ void __launch_bounds__(128) k_attn(
    const float* __restrict__ vectors, const void* __restrict__ maskp,
    const float* __restrict__ We, const float* __restrict__ be,
    const float* __restrict__ g1, const float* __restrict__ b1) {
    extern __shared__ float sm[];
    float* xs   = sm;                  // [128][132]: rows 16B-aligned, conflict-free
    float* vbuf = xs + XS_F;
    float* qg   = vbuf + 1024;         // g1 * qp
    float* As   = qg + 128;            // p_c * rstd_c
    float* red  = As + 128;

    int t = blockIdx.x, r = t >> 4, b = t & 15, tid = threadIdx.x;
    int lane = tid & 31, w = tid >> 5;
    int mode = g_mask_mode;

    { // float4 tile load: 1024 contiguous floats
        const float4* vsrc4 = (const float4*)(vectors + (size_t)(b * Tn + r) * (Tn * In));
        float4* vb4 = (float4*)vbuf;
        vb4[tid] = vsrc4[tid];
        vb4[tid + 128] = vsrc4[tid + 128];
    }
    float qp  = g_Qp[t * 128 + tid];
    float g1v = g1[tid], b1v = b1[tid];
    float qgv = g1v * qp;
    qg[tid] = qgv;
    // block-reduce S1 = sum(g1*qp), C0 = sum(b1*qp)
    {
        float s1p = qgv, c0p = b1v * qp;
#pragma unroll
        for (int o = 16; o > 0; o >>= 1) {
            s1p += __shfl_xor_sync(0xffffffffu, s1p, o);
            c0p += __shfl_xor_sync(0xffffffffu, c0p, o);
        }
        if (lane == 0) { red[w] = s1p; red[4 + w] = c0p; }
    }
    float wcol[8];
#pragma unroll
    for (int i = 0; i < 8; i++) wcol[i] = We[i * 128 + tid];
    float bed = be[tid];
    float mr = mask_at(maskp, (b * Tn + r) * Tn + tid, mode);
    int cnt = __syncthreads_count(mr > 0.f);   // contiguous mask: rows [0,cnt) active
    float S1 = (red[0] + red[1]) + (red[2] + red[3]);
    float C0 = (red[4] + red[5]) + (red[6] + red[7]);

    // Phase A: pre-LN x[c][d] = gelu(v_c @ We + be), only active rows
    {
        const float4* vb4 = (const float4*)vbuf;
        int cnt2 = cnt & ~1;
        for (int c = 0; c < cnt2; c += 2) {
            float4 a0 = vb4[2 * c],     a1 = vb4[2 * c + 1];
            float4 d0 = vb4[2 * c + 2], d1 = vb4[2 * c + 3];
            float e0 = bed, e1 = bed;
            e0 = fmaf(a0.x, wcol[0], e0); e1 = fmaf(d0.x, wcol[0], e1);
            e0 = fmaf(a0.y, wcol[1], e0); e1 = fmaf(d0.y, wcol[1], e1);
            e0 = fmaf(a0.z, wcol[2], e0); e1 = fmaf(d0.z, wcol[2], e1);
            e0 = fmaf(a0.w, wcol[3], e0); e1 = fmaf(d0.w, wcol[3], e1);
            e0 = fmaf(a1.x, wcol[4], e0); e1 = fmaf(d1.x, wcol[4], e1);
            e0 = fmaf(a1.y, wcol[5], e0); e1 = fmaf(d1.y, wcol[5], e1);
            e0 = fmaf(a1.z, wcol[6], e0); e1 = fmaf(d1.z, wcol[6], e1);
            e0 = fmaf(a1.w, wcol[7], e0); e1 = fmaf(d1.w, wcol[7], e1);
            xs[c * 132 + tid]       = gelu_f(e0);
            xs[(c + 1) * 132 + tid] = gelu_f(e1);
        }
        if (cnt & 1) {
            int c = cnt - 1;
            float4 a0 = vb4[2 * c], a1 = vb4[2 * c + 1];
            float e0 = bed;
            e0 = fmaf(a0.x, wcol[0], e0); e0 = fmaf(a0.y, wcol[1], e0);
            e0 = fmaf(a0.z, wcol[2], e0); e0 = fmaf(a0.w, wcol[3], e0);
            e0 = fmaf(a1.x, wcol[4], e0); e0 = fmaf(a1.y, wcol[5], e0);
            e0 = fmaf(a1.z, wcol[6], e0); e0 = fmaf(a1.w, wcol[7], e0);
            xs[c * 132 + tid] = gelu_f(e0);
        }
    }
    __syncthreads();

    // Phase B: fused (sum, sumsq, dot qg) sweep, LN folded into logit
    float s = 0.f, q = 0.f, dot = 0.f;
    {
        int c = tid;
        if (c < cnt) {
            const float4* row4 = (const float4*)(xs + c * 132);
            const float4* qg4  = (const float4*)qg;
            float s0=0,s1=0,s2=0,s3=0, q0=0,q1=0,q2=0,q3=0, t0=0,t1=0,t2=0,t3=0;
#pragma unroll 8
            for (int g = 0; g < 32; g++) {
                float4 xv = row4[g], qv = qg4[g];
                s0 += xv.x; q0 = fmaf(xv.x, xv.x, q0); t0 = fmaf(xv.x, qv.x, t0);
                s1 += xv.y; q1 = fmaf(xv.y, xv.y, q1); t1 = fmaf(xv.y, qv.y, t1);
                s2 += xv.z; q2 = fmaf(xv.z, xv.z, q2); t2 = fmaf(xv.z, qv.z, t2);
                s3 += xv.w; q3 = fmaf(xv.w, xv.w, q3); t3 = fmaf(xv.w, qv.w, t3);
            }
            s = (s0 + s1) + (s2 + s3);
            q = (q0 + q1) + (q2 + q3);
            dot = (t0 + t1) + (t2 + t3);
        }
    }
    float mu   = s * (1.0f / 128.0f);
    float var  = q * (1.0f / 128.0f) - mu * mu;
    float rstd = rsqrtf(var + 1e-5f);
    float logit = (tid < cnt || tid == r) ? fmaf(rstd, dot - mu * S1, C0) : -1e9f;

    // softmax over 128 rows
    float mx = logit;
#pragma unroll
    for (int o = 16; o > 0; o >>= 1) mx = fmaxf(mx, __shfl_xor_sync(0xffffffffu, mx, o));
    if (lane == 0) red[8 + w] = mx;
    __syncthreads();
    mx = fmaxf(fmaxf(red[8], red[9]), fmaxf(red[10], red[11]));

    float p = __expf(logit - mx);
    float A = p * rstd;
    As[tid] = A;
    {
        float ps = p, bp = A * mu;
#pragma unroll
        for (int o = 16; o > 0; o >>= 1) {
            ps += __shfl_xor_sync(0xffffffffu, ps, o);
            bp += __shfl_xor_sync(0xffffffffu, bp, o);
        }
        if (lane == 0) { red[w] = ps; red[4 + w] = bp; }
    }
    __syncthreads();
    float psum = (red[0] + red[1]) + (red[2] + red[3]);
    float beta = (red[4] + red[5]) + (red[6] + red[7]);
    float inv  = __frcp_rn(psum);

    // Phase C: y_d = g1_d * (sum_c A_c x[c][d] - beta)/psum + b1_d
    {
        float y = 0.f;
#pragma unroll 4
        for (int cc = 0; cc < cnt; cc++) y = fmaf(As[cc], xs[cc * 132 + tid], y);
        g_Y[t * 128 + tid] = fmaf(g1v, (y - beta) * inv, b1v);
    }
}

// ---------------- K4: Emb = Y@Wv, H = gelu(Y@M2+bo), out = LN(H+Emb)*seq ----------------
// grid = 256 (8 tokens), block = 256 (half 0: Wv, half 1: M2), register-tiled 4d x 2tok
__global__ void __launch_bounds__(256) k_out(
    const float* __restrict__ Wv, const float* __restrict__ bo,
    const float* __restrict__ g2, const float* __restrict__ b2,
    float* __restrict__ out, int out_size) {
    __shared__ float ys[1024];
    __shared__ float zsE[8 * 128];
    __shared__ float zs[8 * 129];
    int tid = threadIdx.x, t0 = blockIdx.x * 8;

    ((float4*)ys)[tid] = ((const float4*)(g_Y + t0 * 128))[tid];
    __syncthreads();

    int half = tid >> 7, id = tid & 127;
    int dg = id & 31, tg = id >> 5;
    const float4* W4 = (const float4*)(half ? g_M2 : Wv);
    const float* yA = ys + (tg * 2) * 128;
    const float* yB = ys + (tg * 2 + 1) * 128;
    float a0=0,a1=0,a2=0,a3=0, c0=0,c1=0,c2=0,c3=0;
#pragma unroll 8
    for (int e = 0; e < 128; e++) {
        float4 m = W4[e * 32 + dg];
        float ya = yA[e], yb = yB[e];
        a0 = fmaf(ya, m.x, a0); a1 = fmaf(ya, m.y, a1);
        a2 = fmaf(ya, m.z, a2); a3 = fmaf(ya, m.w, a3);
        c0 = fmaf(yb, m.x, c0); c1 = fmaf(yb, m.y, c1);
        c2 = fmaf(yb, m.z, c2); c3 = fmaf(yb, m.w, c3);
    }
    if (half == 0) {
        ((float4*)zsE)[(tg * 2) * 32 + dg]     = make_float4(a0, a1, a2, a3);
        ((float4*)zsE)[(tg * 2 + 1) * 32 + dg] = make_float4(c0, c1, c2, c3);
    }
    __syncthreads();
    if (half == 1) {
        float4 bo4 = ((const float4*)bo)[dg];
        float4 eA = ((const float4*)zsE)[(tg * 2) * 32 + dg];
        float4 eB = ((const float4*)zsE)[(tg * 2 + 1) * 32 + dg];
        int d0 = dg * 4;
        float* rA = zs + (tg * 2) * 129 + d0;
        float* rB = zs + (tg * 2 + 1) * 129 + d0;
        rA[0] = gelu_f(a0 + bo4.x) + eA.x; rA[1] = gelu_f(a1 + bo4.y) + eA.y;
        rA[2] = gelu_f(a2 + bo4.z) + eA.z; rA[3] = gelu_f(a3 + bo4.w) + eA.w;
        rB[0] = gelu_f(c0 + bo4.x) + eB.x; rB[1] = gelu_f(c1 + bo4.y) + eB.y;
        rB[2] = gelu_f(c2 + bo4.z) + eB.z; rB[3] = gelu_f(c3 + bo4.w) + eB.w;
    }
    __syncthreads();

    // LN: warp per token (8 warps, 8 tokens), in-warp reduction only
    if (out_size >= EMB_SZ) {
        int w = tid >> 5, lane = tid & 31;
        float* row = zs + w * 129;
        float v0 = row[lane], v1 = row[lane + 32], v2 = row[lane + 64], v3 = row[lane + 96];
        float s = v0 + v1 + v2 + v3;
        float q = v0 * v0 + v1 * v1 + v2 * v2 + v3 * v3;
#pragma unroll
        for (int o = 16; o > 0; o >>= 1) {
            s += __shfl_xor_sync(0xffffffffu, s, o);
            q += __shfl_xor_sync(0xffffffffu, q, o);
        }
        float mu  = s * (1.0f / 128.0f);
        float var = q * (1.0f / 128.0f) - mu * mu;
        float rstd = rsqrtf(var + 1e-5f);
        float sf = g_seq[t0 + w];
        int ob = (t0 + w) * 128;
        out[ob + lane]      = ((v0 - mu) * rstd * g2[lane]      + b2[lane])      * sf;
        out[ob + lane + 32] = ((v1 - mu) * rstd * g2[lane + 32] + b2[lane + 32]) * sf;
        out[ob + lane + 64] = ((v2 - mu) * rstd * g2[lane + 64] + b2[lane + 64]) * sf;
        out[ob + lane + 96] = ((v3 - mu) * rstd * g2[lane + 96] + b2[lane + 96]) * sf;
    }
}

// ---------------- launch ----------------
extern "C" void kernel_launch(void* const* d_in, const int* in_sizes, int n_in,
                              void* d_out, int out_size) {
    const float* vectors = (const float*)d_in[0];
    const void*  maskp   = d_in[1];
    const float* We = (const float*)d_in[2];
    const float* be = (const float*)d_in[3];
    const float* g1 = (const float*)d_in[4];
    const float* b1 = (const float*)d_in[5];
    const float* Wq = (const float*)d_in[6];
    const float* Wk = (const float*)d_in[7];
    const float* Wv = (const float*)d_in[8];
    const float* Wo = (const float*)d_in[9];
    const float* bo = (const float*)d_in[10];
    const float* g2 = (const float*)d_in[11];
    const float* b2 = (const float*)d_in[12];
    float* out = (float*)d_out;

    int pre_smem = (128 * 129 + 128) * 4;
    cudaFuncSetAttribute(k_precompute, cudaFuncAttributeMaxDynamicSharedMemorySize, pre_smem);
    cudaFuncSetAttribute(k_attn,       cudaFuncAttributeMaxDynamicSharedMemorySize, K3_SMEM);

    k_precompute<<<dim3(128, 2), 128, pre_smem>>>(Wq, Wk, Wv, Wo, maskp);
    k_pre<<<256, 128>>>(vectors, maskp, We, be, g1, b1, out, out_size);
    k_attn<<<NT, 128, K3_SMEM>>>(vectors, maskp, We, be, g1, b1);
    k_out<<<256, 256>>>(Wv, bo, g2, b2, out, out_size);
}

// round 5
// speedup vs baseline: 1.9943x; 1.2064x over previous
#include <cuda_runtime.h>
#include <cuda_bf16.h>

// Shapes
#define Bn 16
#define Tn 128
#define In 8
#define Dn 128
#define NT 2048           // Tn * Bn tokens, t = r*16 + b

// Output packing (fp32 concat of the reference tuple)
#define EMB_SZ   (NT*Dn)        // 262144
#define PAD_OFF  (EMB_SZ)       // padding_mask (B,T)
#define SEQ_OFF  (PAD_OFF+2048) // sequence_mask (T,B,1)
#define GLB_OFF  (SEQ_OFF+2048) // global_mask (T)
#define OUT_ALL  (GLB_OFF+128)  // 266368

// ---------------- scratch (device globals: allocation-free) ----------------
__device__ __align__(16) float g_M1[Dn*Dn];   // Wq @ Wk^T
__device__ __align__(16) float g_M2[Dn*Dn];   // Wv @ W_out
__device__ __align__(16) float g_Qp[NT*Dn];   // LN(diag-x) @ M1 / sqrt(D)
__device__ __align__(16) float g_Y [NT*Dn];   // softmax-weighted LN-combined rows
__device__ float g_seq[NT];     // seq[r,b] as 0/1
__device__ int   g_mask_mode;   // 0=byte, 1=int32, 2=float32

// ---------------- helpers ----------------
__device__ __forceinline__ float gelu_f(float x) {
    float u2 = 1.5957691216057308f * fmaf(0.044715f * x, x * x, x);
    return __fdividef(x, 1.0f + __expf(-u2));
}

__device__ __forceinline__ float mask_at(const void* m, int idx, int mode) {
    if (mode == 0) return ((const unsigned char*)m)[idx] ? 1.0f : 0.0f;
    if (mode == 1) return ((const int*)m)[idx] ? 1.0f : 0.0f;
    return (((const float*)m)[idx] != 0.0f) ? 1.0f : 0.0f;
}

// ---------------- K1: probe + M1 = Wq @ Wk^T ; M2 = Wv @ W_out ----------------
__global__ void k_precompute(const float* __restrict__ Wq, const float* __restrict__ Wk,
                             const float* __restrict__ Wv, const float* __restrict__ Wo,
                             const void* __restrict__ maskp) {
    extern __shared__ float sm[];
    int i = blockIdx.x, j = threadIdx.x;
    if (blockIdx.y == 0) {
        if (i == 0 && j == 0) {
            unsigned int w = *(const unsigned int*)maskp;
            g_mask_mode = (w == 1u) ? 1 : ((w == 0x3F800000u) ? 2 : 0);
        }
        float* wks  = sm;               // [128][129] padded
        float* rowq = sm + 128 * 129;
        for (int idx = j; idx < 128 * 128; idx += 128) {
            int rr = idx >> 7, cc = idx & 127;
            wks[rr * 129 + cc] = Wk[idx];
        }
        rowq[j] = Wq[i * 128 + j];
        __syncthreads();
        float acc = 0.f;
#pragma unroll 8
        for (int k = 0; k < 128; k++) acc += rowq[k] * wks[j * 129 + k];
        g_M1[i * 128 + j] = acc;
    } else {
        float* rowv = sm;
        rowv[j] = Wv[i * 128 + j];
        __syncthreads();
        float acc = 0.f;
#pragma unroll 8
        for (int k = 0; k < 128; k++) acc += rowv[k] * Wo[k * 128 + j];
        g_M2[i * 128 + j] = acc;
    }
}

// ---------------- K2: diag tokens -> LN -> Qp, + mask outputs ----------------
__global__ void __launch_bounds__(128) k_pre(
    const float* __restrict__ vectors, const void* __restrict__ maskp,
    const float* __restrict__ We, const float* __restrict__ be,
    const float* __restrict__ g1, const float* __restrict__ b1,
    float* __restrict__ out, int out_size) {
    __shared__ float vs[64];
    __shared__ float mval[8];
    __shared__ float xds[8 * 128];
    int r = blockIdx.x >> 1, bb = (blockIdx.x & 1) << 3;
    int tid = threadIdx.x, lane = tid & 31, w = tid >> 5;
    int mode = g_mask_mode;

    if (tid < 64) {
        int tt = tid >> 3, i = tid & 7;
        vs[tid] = vectors[(((((bb + tt) * Tn + r) * Tn) + r) << 3) + i];
    }
    if (tid < 8) mval[tid] = mask_at(maskp, ((bb + tid) * Tn + r) * Tn + r, mode);
    float wcol[8];
#pragma unroll
    for (int i = 0; i < 8; i++) wcol[i] = We[i * 128 + tid];
    float bed = be[tid];
    __syncthreads();

#pragma unroll
    for (int tt = 0; tt < 8; tt++) {
        float e = bed;
#pragma unroll
        for (int i = 0; i < 8; i++) e = fmaf(vs[tt * 8 + i], wcol[i], e);
        xds[tt * 128 + tid] = gelu_f(e) * mval[tt];
    }
    __syncthreads();

    {
        float g1r0 = g1[lane], g1r1 = g1[lane + 32], g1r2 = g1[lane + 64], g1r3 = g1[lane + 96];
        float b1r0 = b1[lane], b1r1 = b1[lane + 32], b1r2 = b1[lane + 64], b1r3 = b1[lane + 96];
        for (int tt = w; tt < 8; tt += 4) {
            float* row = xds + tt * 128;
            float v0 = row[lane], v1 = row[lane + 32], v2 = row[lane + 64], v3 = row[lane + 96];
            float s = v0 + v1 + v2 + v3;
            float q = v0 * v0 + v1 * v1 + v2 * v2 + v3 * v3;
#pragma unroll
            for (int o = 16; o > 0; o >>= 1) {
                s += __shfl_xor_sync(0xffffffffu, s, o);
                q += __shfl_xor_sync(0xffffffffu, q, o);
            }
            float mu  = s * (1.0f / 128.0f);
            float var = q * (1.0f / 128.0f) - mu * mu;
            float rstd = rsqrtf(var + 1e-5f);
            row[lane]      = (v0 - mu) * rstd * g1r0 + b1r0;
            row[lane + 32] = (v1 - mu) * rstd * g1r1 + b1r1;
            row[lane + 64] = (v2 - mu) * rstd * g1r2 + b1r2;
            row[lane + 96] = (v3 - mu) * rstd * g1r3 + b1r3;
        }
    }
    __syncthreads();

    {
        int dg = tid & 31, tg = tid >> 5;
        const float4* M14 = (const float4*)g_M1;
        const float* yA = xds + (tg * 2) * 128;
        const float* yB = xds + (tg * 2 + 1) * 128;
        float a0 = 0, a1 = 0, a2 = 0, a3 = 0, c0 = 0, c1 = 0, c2 = 0, c3 = 0;
#pragma unroll 8
        for (int e = 0; e < 128; e++) {
            float4 m = M14[e * 32 + dg];
            float ya = yA[e], yb = yB[e];
            a0 = fmaf(ya, m.x, a0); a1 = fmaf(ya, m.y, a1);
            a2 = fmaf(ya, m.z, a2); a3 = fmaf(ya, m.w, a3);
            c0 = fmaf(yb, m.x, c0); c1 = fmaf(yb, m.y, c1);
            c2 = fmaf(yb, m.z, c2); c3 = fmaf(yb, m.w, c3);
        }
        const float sc = 0.08838834764831845f;
        int tokA = (r << 4) + bb + tg * 2;
        float4* Qp4 = (float4*)g_Qp;
        Qp4[tokA * 32 + dg]       = make_float4(a0 * sc, a1 * sc, a2 * sc, a3 * sc);
        Qp4[(tokA + 1) * 32 + dg] = make_float4(c0 * sc, c1 * sc, c2 * sc, c3 * sc);
    }

    if (tid < 8) {
        float sval = mval[tid];
        int t = (r << 4) + bb + tid;
        g_seq[t] = sval;
        if (out_size >= SEQ_OFF) out[PAD_OFF + (bb + tid) * Tn + r] = (sval > 0.f) ? 0.f : 1.f;
        if (out_size >= GLB_OFF) out[SEQ_OFF + t] = sval;
    }
    if (tid == 0 && bb == 0 && out_size >= OUT_ALL) out[GLB_OFF + r] = 1.0f;
}

// ---------------- K3: fused embed+attention, LN folded, 256 threads ----------------
// row stride 136 floats: phase-B paired-lane even/odd-float4 access is conflict-free
#define XSTR   136
#define XS_F   (128*XSTR)
// dynamic smem floats: xs | vbuf(1024, aliased by ypart 256 after phase A) | qg 128 | As 128
#define K3_SMEM ((XS_F + 1024 + 128 + 128) * 4)
__global__ void __launch_bounds__(256) k_attn(
    const float* __restrict__ vectors, const void* __restrict__ maskp,
    const float* __restrict__ We, const float* __restrict__ be,
    const float* __restrict__ g1, const float* __restrict__ b1) {
    extern __shared__ float sm[];
    float* xs    = sm;
    float* vbuf  = xs + XS_F;       // phase A only
    float* ypart = vbuf;            // alias: phase C partials [2][128]
    float* qg    = vbuf + 1024;     // g1 * qp
    float* As    = qg + 128;        // p_c * rstd_c
    __shared__ float sred[16];

    int t = blockIdx.x, r = t >> 4, b = t & 15, tid = threadIdx.x;
    int lane = tid & 31, w = tid >> 5;
    int d = tid & 127, h = tid >> 7;      // phase A/C split
    int mode = g_mask_mode;

    { // float4 tile load: 1024 contiguous floats, 256 threads x 1
        const float4* vsrc4 = (const float4*)(vectors + (size_t)(b * Tn + r) * (Tn * In));
        ((float4*)vbuf)[tid] = vsrc4[tid];
    }
    float qp  = g_Qp[t * 128 + d];
    float g1v = g1[d], b1v = b1[d];
    float qgv = g1v * qp;
    if (h == 0) qg[d] = qgv;
    { // S1 = sum(g1*qp), C0 = sum(b1*qp): gated to half 0, reduced over 8 warps
        float s1p = (h == 0) ? qgv : 0.f;
        float c0p = (h == 0) ? b1v * qp : 0.f;
#pragma unroll
        for (int o = 16; o > 0; o >>= 1) {
            s1p += __shfl_xor_sync(0xffffffffu, s1p, o);
            c0p += __shfl_xor_sync(0xffffffffu, c0p, o);
        }
        if (lane == 0) { sred[w] = s1p; sred[8 + w] = c0p; }
    }
    float wcol[8];
#pragma unroll
    for (int i = 0; i < 8; i++) wcol[i] = We[i * 128 + d];
    float bed = be[d];
    float mr = mask_at(maskp, (b * Tn + r) * Tn + d, mode);
    int cnt = __syncthreads_count(mr > 0.f) >> 1;   // both halves counted
    float S1 = ((sred[0] + sred[1]) + (sred[2] + sred[3]))
             + ((sred[4] + sred[5]) + (sred[6] + sred[7]));
    float C0 = ((sred[8] + sred[9]) + (sred[10] + sred[11]))
             + ((sred[12] + sred[13]) + (sred[14] + sred[15]));

    // Phase A: x[c][d] = gelu(v_c @ We + be), half h does rows c === h (mod 2)
    {
        const float4* vb4 = (const float4*)vbuf;
        for (int c = h; c < cnt; c += 2) {
            float4 a0 = vb4[2 * c], a1 = vb4[2 * c + 1];
            float e0 = bed;
            e0 = fmaf(a0.x, wcol[0], e0); e0 = fmaf(a0.y, wcol[1], e0);
            e0 = fmaf(a0.z, wcol[2], e0); e0 = fmaf(a0.w, wcol[3], e0);
            e0 = fmaf(a1.x, wcol[4], e0); e0 = fmaf(a1.y, wcol[5], e0);
            e0 = fmaf(a1.z, wcol[6], e0); e0 = fmaf(a1.w, wcol[7], e0);
            xs[c * XSTR + d] = gelu_f(e0);
        }
    }
    __syncthreads();

    // Phase B: lane pair (c = tid>>1, hh = tid&1) splits the 128-dot by float4 parity
    int c = tid >> 1, hh = tid & 1;
    float s = 0.f, q = 0.f, dot = 0.f;
    if (c < cnt) {
        const float4* row4 = (const float4*)(xs + c * XSTR);
        const float4* qg4  = (const float4*)qg;
        float s0=0,s1=0, q0=0,q1=0, t0=0,t1=0;
#pragma unroll 8
        for (int g = 0; g < 16; g++) {
            int j = 2 * g + hh;
            float4 xv = row4[j], qv = qg4[j];
            s0 += xv.x; q0 = fmaf(xv.x, xv.x, q0); t0 = fmaf(xv.x, qv.x, t0);
            s1 += xv.y; q1 = fmaf(xv.y, xv.y, q1); t1 = fmaf(xv.y, qv.y, t1);
            s0 += xv.z; q0 = fmaf(xv.z, xv.z, q0); t0 = fmaf(xv.z, qv.z, t0);
            s1 += xv.w; q1 = fmaf(xv.w, xv.w, q1); t1 = fmaf(xv.w, qv.w, t1);
        }
        s = s0 + s1; q = q0 + q1; dot = t0 + t1;
    }
    s   += __shfl_xor_sync(0xffffffffu, s, 1);
    q   += __shfl_xor_sync(0xffffffffu, q, 1);
    dot += __shfl_xor_sync(0xffffffffu, dot, 1);

    float mu   = s * (1.0f / 128.0f);
    float var  = q * (1.0f / 128.0f) - mu * mu;
    float rstd = rsqrtf(var + 1e-5f);
    float logit = (c < cnt || c == r) ? fmaf(rstd, dot - mu * S1, C0) : -1e9f;

    // softmax over 128 rows (each c held by 2 threads; sums gated to hh==0)
    float mx = logit;
#pragma unroll
    for (int o = 16; o > 0; o >>= 1) mx = fmaxf(mx, __shfl_xor_sync(0xffffffffu, mx, o));
    if (lane == 0) sred[w] = mx;
    __syncthreads();
    mx = fmaxf(fmaxf(fmaxf(sred[0], sred[1]), fmaxf(sred[2], sred[3])),
               fmaxf(fmaxf(sred[4], sred[5]), fmaxf(sred[6], sred[7])));

    float p = __expf(logit - mx);
    float A = p * rstd;
    if (hh == 0) As[c] = A;
    {
        float ps = (hh == 0) ? p : 0.f;
        float bp = (hh == 0) ? A * mu : 0.f;
#pragma unroll
        for (int o = 16; o > 0; o >>= 1) {
            ps += __shfl_xor_sync(0xffffffffu, ps, o);
            bp += __shfl_xor_sync(0xffffffffu, bp, o);
        }
        if (lane == 0) { sred[w] = ps; sred[8 + w] = bp; }
    }
    __syncthreads();
    float psum = ((sred[0] + sred[1]) + (sred[2] + sred[3]))
               + ((sred[4] + sred[5]) + (sred[6] + sred[7]));
    float beta = ((sred[8] + sred[9]) + (sred[10] + sred[11]))
               + ((sred[12] + sred[13]) + (sred[14] + sred[15]));
    float inv  = __frcp_rn(psum);

    // Phase C: half h sums rows of its parity, combine via ypart (aliases vbuf)
    {
        float y = 0.f;
#pragma unroll 4
        for (int cc = h; cc < cnt; cc += 2) y = fmaf(As[cc], xs[cc * XSTR + d], y);
        __syncthreads();             // vbuf dead; safe to overwrite
        ypart[h * 128 + d] = y;
    }
    __syncthreads();
    if (h == 0) {
        float y = ypart[d] + ypart[128 + d];
        g_Y[t * 128 + d] = fmaf(g1v, (y - beta) * inv, b1v);
    }
}

// ---------------- K4: Emb = Y@Wv, H = gelu(Y@M2+bo), out = LN(H+Emb)*seq ----------------
// grid 512 (4 tokens/block), block 256: half = matrix, dg = d-quad, es = e-chunk(32)
__global__ void __launch_bounds__(256) k_out(
    const float* __restrict__ Wv, const float* __restrict__ bo,
    const float* __restrict__ g2, const float* __restrict__ b2,
    float* __restrict__ out, int out_size) {
    __shared__ float ys[512];
    __shared__ float zpf[4096];     // [half][es][tok][128 d]
    __shared__ float zs[4 * 129];
    int tid = threadIdx.x, t0 = blockIdx.x * 4;
    int half = tid >> 7, id = tid & 127, dg = id & 31, es = id >> 5;

    if (tid < 128) ((float4*)ys)[tid] = ((const float4*)(g_Y + t0 * 128))[tid];
    __syncthreads();

    const float4* W4 = (const float4*)(half ? g_M2 : Wv);
    float4 a0 = {0,0,0,0}, a1 = {0,0,0,0}, a2 = {0,0,0,0}, a3 = {0,0,0,0};
    int e0 = es * 32;
#pragma unroll 4
    for (int e = e0; e < e0 + 32; e++) {
        float4 m = W4[e * 32 + dg];
        float y0 = ys[e], y1 = ys[128 + e], y2 = ys[256 + e], y3 = ys[384 + e];
        a0.x = fmaf(y0, m.x, a0.x); a0.y = fmaf(y0, m.y, a0.y);
        a0.z = fmaf(y0, m.z, a0.z); a0.w = fmaf(y0, m.w, a0.w);
        a1.x = fmaf(y1, m.x, a1.x); a1.y = fmaf(y1, m.y, a1.y);
        a1.z = fmaf(y1, m.z, a1.z); a1.w = fmaf(y1, m.w, a1.w);
        a2.x = fmaf(y2, m.x, a2.x); a2.y = fmaf(y2, m.y, a2.y);
        a2.z = fmaf(y2, m.z, a2.z); a2.w = fmaf(y2, m.w, a2.w);
        a3.x = fmaf(y3, m.x, a3.x); a3.y = fmaf(y3, m.y, a3.y);
        a3.z = fmaf(y3, m.z, a3.z); a3.w = fmaf(y3, m.w, a3.w);
    }
    {
        float4* zp4 = (float4*)zpf;
        int base = ((half * 4 + es) * 4) * 32 + dg;
        zp4[base]      = a0;
        zp4[base + 32] = a1;
        zp4[base + 64] = a2;
        zp4[base + 96] = a3;
    }
    __syncthreads();

    // reduce across es, combine E/H, gelu+residual -> zs
#pragma unroll
    for (int pp = 0; pp < 2; pp++) {
        int p = tid + pp * 256;          // (tok, d) pair, 512 total
        int tok = p >> 7, dd = p & 127;
        float E = 0.f, H = 0.f;
#pragma unroll
        for (int e2 = 0; e2 < 4; e2++) {
            E += zpf[((0 * 4 + e2) * 4 + tok) * 128 + dd];
            H += zpf[((1 * 4 + e2) * 4 + tok) * 128 + dd];
        }
        zs[tok * 129 + dd] = gelu_f(H + bo[dd]) + E;
    }
    __syncthreads();

    // LN: warp per token (warps 0-3)
    if (out_size >= EMB_SZ && tid < 128) {
        int w = tid >> 5, lane = tid & 31;
        float* row = zs + w * 129;
        float v0 = row[lane], v1 = row[lane + 32], v2 = row[lane + 64], v3 = row[lane + 96];
        float s = v0 + v1 + v2 + v3;
        float q = v0 * v0 + v1 * v1 + v2 * v2 + v3 * v3;
#pragma unroll
        for (int o = 16; o > 0; o >>= 1) {
            s += __shfl_xor_sync(0xffffffffu, s, o);
            q += __shfl_xor_sync(0xffffffffu, q, o);
        }
        float mu  = s * (1.0f / 128.0f);
        float var = q * (1.0f / 128.0f) - mu * mu;
        float rstd = rsqrtf(var + 1e-5f);
        float sf = g_seq[t0 + w];
        int ob = (t0 + w) * 128;
        out[ob + lane]      = ((v0 - mu) * rstd * g2[lane]      + b2[lane])      * sf;
        out[ob + lane + 32] = ((v1 - mu) * rstd * g2[lane + 32] + b2[lane + 32]) * sf;
        out[ob + lane + 64] = ((v2 - mu) * rstd * g2[lane + 64] + b2[lane + 64]) * sf;
        out[ob + lane + 96] = ((v3 - mu) * rstd * g2[lane + 96] + b2[lane + 96]) * sf;
    }
}

// ---------------- launch ----------------
extern "C" void kernel_launch(void* const* d_in, const int* in_sizes, int n_in,
                              void* d_out, int out_size) {
    const float* vectors = (const float*)d_in[0];
    const void*  maskp   = d_in[1];
    const float* We = (const float*)d_in[2];
    const float* be = (const float*)d_in[3];
    const float* g1 = (const float*)d_in[4];
    const float* b1 = (const float*)d_in[5];
    const float* Wq = (const float*)d_in[6];
    const float* Wk = (const float*)d_in[7];
    const float* Wv = (const float*)d_in[8];
    const float* Wo = (const float*)d_in[9];
    const float* bo = (const float*)d_in[10];
    const float* g2 = (const float*)d_in[11];
    const float* b2 = (const float*)d_in[12];
    float* out = (float*)d_out;

    int pre_smem = (128 * 129 + 128) * 4;
    cudaFuncSetAttribute(k_precompute, cudaFuncAttributeMaxDynamicSharedMemorySize, pre_smem);
    cudaFuncSetAttribute(k_attn,       cudaFuncAttributeMaxDynamicSharedMemorySize, K3_SMEM);

    k_precompute<<<dim3(128, 2), 128, pre_smem>>>(Wq, Wk, Wv, Wo, maskp);
    k_pre<<<256, 128>>>(vectors, maskp, We, be, g1, b1, out, out_size);
    k_attn<<<NT, 256, K3_SMEM>>>(vectors, maskp, We, be, g1, b1);
    k_out<<<512, 256>>>(Wv, bo, g2, b2, out, out_size);
}